// round 15
// baseline (speedup 1.0000x reference)
#include <cuda_runtime.h>
#include <cuda_bf16.h>
#include <math.h>
#include <stdint.h>

#define Bsz   4
#define Nseq  2048
#define Dm    513
#define Hh    8
#define Mrows 8192
#define KPAD  576
#define INVK  10.0f
#define KCURV 0.1f
#define EPSf  1e-9f
#define S2f   0.18033688011112042f   // 0.125 * log2(e)

// ---------------- device scratch ----------------
__device__ float OutCat[(size_t)Mrows*512];
__device__ float HSS[Mrows*Hh];
__device__ float Part2[Mrows*8];
__device__ __nv_bfloat16 Xhi[(size_t)Mrows*KPAD];
__device__ __nv_bfloat16 Xlo[(size_t)Mrows*KPAD];
__device__ __nv_bfloat16 WqkvHi[24*64*KPAD];
__device__ __nv_bfloat16 WqkvLo[24*64*KPAD];
__device__ __nv_bfloat16 WoTHi[512*KPAD];
__device__ __nv_bfloat16 WoTLo[512*KPAD];
__device__ __nv_bfloat16 Chi[(size_t)Mrows*KPAD];
__device__ __nv_bfloat16 Clo[(size_t)Mrows*KPAD];
__device__ uint32_t QKiW[(size_t)32*2048*64];
__device__ uint32_t KKiW[(size_t)32*2048*64];
__device__ float Tqg[32*2048];
__device__ float Tkg[32*2048];
__device__ __nv_bfloat16 Vh_[(size_t)32*2048*65];
__device__ __nv_bfloat16 Vl_[(size_t)32*2048*65];
__device__ __nv_bfloat16 VTiE[(size_t)32*72*32*128];

__device__ __forceinline__ void bsplit(float v, __nv_bfloat16& h, __nv_bfloat16& l) {
    h = __float2bfloat16(v);
    l = __float2bfloat16(v - __bfloat162float(h));
}
__device__ __forceinline__ uint32_t pack2(__nv_bfloat16 a, __nv_bfloat16 b) {
    __nv_bfloat162 t2; t2.x = a; t2.y = b;
    uint32_t r; memcpy(&r, &t2, 4); return r;
}
__device__ __forceinline__ uint32_t cvtpk(float lo, float hi) {
    uint32_t r;
    asm("cvt.rn.bf16x2.f32 %0, %1, %2;" : "=r"(r) : "f"(hi), "f"(lo));
    return r;
}

__device__ __forceinline__ float exp2p(float y) {
    y = fmaxf(y, -120.f);
    float z = y + 12582912.f;
    int ib = __float_as_int(z);
    float n = z - 12582912.f;
    float f = y - n;
    float p = 1.3333558146e-3f;
    p = fmaf(p, f, 9.6181291076e-3f);
    p = fmaf(p, f, 5.5504108664e-2f);
    p = fmaf(p, f, 2.4022650696e-1f);
    p = fmaf(p, f, 6.9314718056e-1f);
    p = fmaf(p, f, 1.0f);
    return __int_as_float(__float_as_int(p) + (ib << 23));
}

#define MMA16816(D, A, B) \
    asm volatile("mma.sync.aligned.m16n8k16.row.col.f32.bf16.bf16.f32 " \
        "{%0,%1,%2,%3}, {%4,%5,%6,%7}, {%8,%9}, {%0,%1,%2,%3};" \
        : "+f"((D)[0]), "+f"((D)[1]), "+f"((D)[2]), "+f"((D)[3]) \
        : "r"((A)[0]), "r"((A)[1]), "r"((A)[2]), "r"((A)[3]), \
          "r"((B)[0]), "r"((B)[1]))

#define CP_ASYNC16(dst, src) \
    asm volatile("cp.async.cg.shared.global [%0], [%1], 16;" :: "r"(dst), "l"(src))
#define CP_COMMIT() asm volatile("cp.async.commit_group;" ::: "memory")
#define CP_WAIT(n)  asm volatile("cp.async.wait_group %0;" :: "n"(n) : "memory")

// projection GEMM smem geometry (words); double-buffered
#define RS 36
#define GA_HI 0
#define GA_LO 4608
#define GB_HI 9216
#define GB_LO 11520
#define GBUF  13824
#define WBIAS 27648
#define WSSP  27712
#define WTOT  27968

// attention smem geometry (words)
#define RSA   80
#define VOFF  5120
#define TKOFF 10880
#define ABUF  10944

__device__ __forceinline__ int ipos(int j) {
    return 16 * (j >> 3) + 4 * (j & 3) + ((j >> 2) & 1);
}
__device__ __forceinline__ uint32_t smem_u32(const void* p) {
    uint32_t a;
    asm("{ .reg .u64 t; cvta.to.shared.u64 t, %1; cvt.u32.u64 %0, t; }" : "=r"(a) : "l"(p));
    return a;
}

// =====================================================================
// input conversion (row-indexed, proven)
// =====================================================================
__global__ __launch_bounds__(576) void cvt_in_kernel(
    const float* __restrict__ Wq, const float* __restrict__ Wk,
    const float* __restrict__ Wv, const float* __restrict__ Wo,
    const float* __restrict__ x)
{
    const int bid = blockIdx.x;
    const int k = threadIdx.x;
    if (bid < 1536) {
        int n = bid & 63;
        int s = bid >> 6;
        int which = s >> 3, h = s & 7;
        const float* W = (which == 0) ? Wq : (which == 1) ? Wk : Wv;
        float v = (k < Dm) ? W[((size_t)h * Dm + k) * 64 + n] : 0.f;
        size_t i = (size_t)bid * KPAD + k;
        bsplit(v, WqkvHi[i], WqkvLo[i]);
    } else if (bid < 2048) {
        int n = bid - 1536;
        float v = (k < Dm) ? Wo[(size_t)k * 512 + n] : 0.f;
        size_t i = (size_t)n * KPAD + k;
        bsplit(v, WoTHi[i], WoTLo[i]);
    } else {
        size_t row = bid - 2048;
        float v = (k < Dm) ? x[row * Dm + k] : 0.f;
        size_t i = row * KPAD + k;
        bsplit(v, Xhi[i], Xlo[i]);
    }
}

__global__ __launch_bounds__(576) void cvt_cat_kernel()
{
    const size_t row = blockIdx.x;
    const int k = threadIdx.x;
    float v;
    if (k == 0) {
        float ss = 0.f;
        #pragma unroll
        for (int hh = 0; hh < 8; hh++) ss += HSS[row * 8 + hh];
        v = sqrtf(fmaxf(INVK + ss, EPSf));
    } else if (k < Dm) {
        v = OutCat[row * 512 + k - 1];
    } else v = 0.f;
    size_t i = row * KPAD + k;
    bsplit(v, Chi[i], Clo[i]);
}

// =====================================================================
// pipelined projection GEMM mainloop (single-sync double buffer)
// =====================================================================
__device__ __forceinline__ void gemm_issue_chunk(
    uint32_t smb, int bufw, int k0, int tid,
    const __nv_bfloat16* __restrict__ Ah, const __nv_bfloat16* __restrict__ Al,
    const __nv_bfloat16* __restrict__ Bh, const __nv_bfloat16* __restrict__ Bl)
{
    for (int i = tid; i < 3072; i += 256) {
        uint32_t dstw; const void* src;
        if (i < 1024) {
            int r = i >> 3, q = i & 7;
            dstw = bufw + GA_HI + r * RS + q * 4;
            src = Ah + (size_t)r * KPAD + k0 + q * 8;
        } else if (i < 2048) {
            int j = i - 1024, r = j >> 3, q = j & 7;
            dstw = bufw + GA_LO + r * RS + q * 4;
            src = Al + (size_t)r * KPAD + k0 + q * 8;
        } else if (i < 2560) {
            int j = i - 2048, r = j >> 3, q = j & 7;
            dstw = bufw + GB_HI + r * RS + q * 4;
            src = Bh + (size_t)r * KPAD + k0 + q * 8;
        } else {
            int j = i - 2560, r = j >> 3, q = j & 7;
            dstw = bufw + GB_LO + r * RS + q * 4;
            src = Bl + (size_t)r * KPAD + k0 + q * 8;
        }
        CP_ASYNC16(smb + dstw * 4, src);
    }
}

__device__ __forceinline__ void gemm_mainloop(
    uint32_t* smw, int tid,
    const __nv_bfloat16* Ah, const __nv_bfloat16* Al,
    const __nv_bfloat16* Bh, const __nv_bfloat16* Bl,
    float acc[2][4][4])
{
    const int wid = tid >> 5, lane = tid & 31;
    const int wm = wid & 3, wn = wid >> 2;
    const int g = lane >> 2, t = lane & 3;
    const uint32_t smb = smem_u32(smw);

    gemm_issue_chunk(smb, 0, 0, tid, Ah, Al, Bh, Bl);
    CP_COMMIT();

    for (int c = 0; c < 9; c++) {
        const int cur = (c & 1) * GBUF;
        CP_WAIT(0);
        __syncthreads();
        if (c < 8) {
            gemm_issue_chunk(smb, ((c + 1) & 1) * GBUF, (c + 1) * 64, tid, Ah, Al, Bh, Bl);
            CP_COMMIT();
        }

        #pragma unroll
        for (int ks = 0; ks < 4; ks++) {
            uint32_t ah[2][4], al[2][4], bh[4][2], bl[4][2];
            const int kw = ks * 8 + t;
            #pragma unroll
            for (int mt = 0; mt < 2; mt++) {
                int r = wm * 32 + mt * 16 + g;
                ah[mt][0] = smw[cur + GA_HI + r * RS + kw];
                ah[mt][1] = smw[cur + GA_HI + (r + 8) * RS + kw];
                ah[mt][2] = smw[cur + GA_HI + r * RS + kw + 4];
                ah[mt][3] = smw[cur + GA_HI + (r + 8) * RS + kw + 4];
                al[mt][0] = smw[cur + GA_LO + r * RS + kw];
                al[mt][1] = smw[cur + GA_LO + (r + 8) * RS + kw];
                al[mt][2] = smw[cur + GA_LO + r * RS + kw + 4];
                al[mt][3] = smw[cur + GA_LO + (r + 8) * RS + kw + 4];
            }
            #pragma unroll
            for (int nt = 0; nt < 4; nt++) {
                int n = wn * 32 + nt * 8 + g;
                bh[nt][0] = smw[cur + GB_HI + n * RS + kw];
                bh[nt][1] = smw[cur + GB_HI + n * RS + kw + 4];
                bl[nt][0] = smw[cur + GB_LO + n * RS + kw];
                bl[nt][1] = smw[cur + GB_LO + n * RS + kw + 4];
            }
            #pragma unroll
            for (int mt = 0; mt < 2; mt++)
                #pragma unroll
                for (int nt = 0; nt < 4; nt++) {
                    MMA16816(acc[mt][nt], ah[mt], bh[nt]);
                    MMA16816(acc[mt][nt], ah[mt], bl[nt]);
                    MMA16816(acc[mt][nt], al[mt], bh[nt]);
                }
        }
    }
    __syncthreads();
}

// =====================================================================
// K1: QKV GEMM (epilogue unchanged)
// =====================================================================
__global__ __launch_bounds__(256) void qkv_mma(
    const float* __restrict__ bq, const float* __restrict__ bk, const float* __restrict__ bv)
{
    extern __shared__ uint32_t smw[];
    const int tid = threadIdx.x;
    const int wid = tid >> 5, lane = tid & 31;
    const int wm = wid & 3, wn = wid >> 2;
    const int g = lane >> 2, t = lane & 3;
    const int which = blockIdx.y % 3;
    const int h     = blockIdx.y / 3;
    const int slot  = which * 8 + h;
    const int m0    = blockIdx.x * 128;

    {
        const float* bias = (which == 0) ? bq : (which == 1) ? bk : bv;
        if (tid < 64) ((float*)(smw + WBIAS))[tid] = bias[h * 64 + tid];
    }

    float acc[2][4][4];
    #pragma unroll
    for (int mt = 0; mt < 2; mt++)
        #pragma unroll
        for (int nt = 0; nt < 4; nt++)
            #pragma unroll
            for (int i = 0; i < 4; i++) acc[mt][nt][i] = 0.f;

    gemm_mainloop(smw, tid,
                  Xhi + (size_t)m0 * KPAD, Xlo + (size_t)m0 * KPAD,
                  WqkvHi + (size_t)slot * 64 * KPAD, WqkvLo + (size_t)slot * 64 * KPAD,
                  acc);

    const float* biass = (const float*)(smw + WBIAS);
    float* ssP = (float*)(smw + WSSP);

    #pragma unroll
    for (int mt = 0; mt < 2; mt++) {
        #pragma unroll
        for (int half = 0; half < 2; half++) {
            int lrow = wm * 32 + mt * 16 + g + half * 8;
            int row = m0 + lrow;
            int b = row >> 11, n = row & (Nseq - 1);
            size_t rbase = (size_t)(b * 8 + h) * 2048 + n;
            float ss = 0.f;
            #pragma unroll
            for (int nt = 0; nt < 4; nt++) {
                int col0 = wn * 32 + nt * 8 + 2 * t;
                float v0 = acc[mt][nt][half * 2 + 0] + biass[col0];
                float v1 = acc[mt][nt][half * 2 + 1] + biass[col0 + 1];
                ss += v0 * v0 + v1 * v1;
                __nv_bfloat16 h0, l0, h1, l1;
                bsplit(v0, h0, l0); bsplit(v1, h1, l1);
                if (which == 2) {
                    Vh_[rbase * 65 + 1 + col0] = h0;  Vh_[rbase * 65 + 2 + col0] = h1;
                    Vl_[rbase * 65 + 1 + col0] = l0;  Vl_[rbase * 65 + 2 + col0] = l1;
                } else {
                    int j = col0 >> 1;
                    int pos = ipos(j);
                    uint32_t* dst = (which == 0) ? QKiW : KKiW;
                    dst[rbase * 64 + pos]     = pack2(h0, h1);
                    dst[rbase * 64 + pos + 2] = pack2(l0, l1);
                }
            }
            ss += __shfl_xor_sync(0xffffffffu, ss, 1);
            ss += __shfl_xor_sync(0xffffffffu, ss, 2);
            if (t == 0) ssP[lrow * 2 + wn] = ss;
        }
    }
    __syncthreads();
    if (wn == 0 && t == 0) {
        #pragma unroll
        for (int mt = 0; mt < 2; mt++)
            #pragma unroll
            for (int half = 0; half < 2; half++) {
                int lrow = wm * 32 + mt * 16 + g + half * 8;
                int row = m0 + lrow;
                int b = row >> 11, n = row & (Nseq - 1);
                size_t rbase = (size_t)(b * 8 + h) * 2048 + n;
                float ss = ssP[lrow * 2] + ssP[lrow * 2 + 1];
                float tv = sqrtf(fmaxf(INVK + ss, EPSf));
                if (which == 0) Tqg[rbase] = tv;
                else if (which == 1) Tkg[rbase] = tv;
                else { bsplit(tv, Vh_[rbase * 65], Vl_[rbase * 65]); }
            }
    }
}

// =====================================================================
// V transpose (unchanged)
// =====================================================================
__global__ __launch_bounds__(128) void vtrans()
{
    __shared__ __nv_bfloat16 sh[64][73];
    __shared__ __nv_bfloat16 sl[64][73];
    const int bh = blockIdx.y, k0 = blockIdx.x * 64, tid = threadIdx.x;
    const int blk = blockIdx.x;
    const __nv_bfloat16 z = __float2bfloat16(0.f);
    for (int i = tid; i < 64 * 72; i += 128) {
        int r = i / 72, d = i % 72;
        sh[r][d] = (d < 65) ? Vh_[((size_t)bh * 2048 + k0 + r) * 65 + d] : z;
        sl[r][d] = (d < 65) ? Vl_[((size_t)bh * 2048 + k0 + r) * 65 + d] : z;
    }
    __syncthreads();
    for (int i = tid; i < 72 * 64; i += 128) {
        int d = i >> 6, k = i & 63;
        int jj = k >> 1, e = k & 1;
        int pos = ipos(jj);
        size_t eb = (((size_t)bh * 72 + d) * 32 + blk) * 128;
        VTiE[eb + pos * 2 + e]       = sh[k][d];
        VTiE[eb + (pos + 2) * 2 + e] = sl[k][d];
    }
}

// =====================================================================
// K2: pipelined flash attention; QK = qh·kh + qh·kl (q_lo dropped),
// single sync per tile.
// =====================================================================
__device__ __forceinline__ void attn_issue_tile(
    uint32_t smb, int bufw, int kt, int tid, int bh, size_t base)
{
    const int k0 = kt * 64;
    for (int i = tid; i < 2192; i += 256) {
        uint32_t dstw; const void* src;
        if (i < 1024) {
            int r = i >> 4, ch = i & 15;
            dstw = bufw + r * RSA + ch * 4;
            src = KKiW + (base + k0 + r) * 64 + ch * 4;
        } else if (i < 2176) {
            int j = i - 1024, d = j >> 4, ch = j & 15;
            dstw = bufw + VOFF + d * RSA + ch * 4;
            src = VTiE + (((size_t)bh * 72 + d) * 32 + kt) * 128 + ch * 8;
        } else {
            int j = i - 2176;
            dstw = bufw + TKOFF + j * 4;
            src = Tkg + base + k0 + j * 4;
        }
        CP_ASYNC16(smb + dstw * 4, src);
    }
}

__global__ __launch_bounds__(256, 2) void attn_mma()
{
    extern __shared__ uint32_t sw[];
    const int tid = threadIdx.x;
    const int w = tid >> 5, lane = tid & 31;
    const int g = lane >> 2, t = lane & 3;
    const int bh = blockIdx.y;
    const int b = bh >> 3, h = bh & 7;
    const int n0 = blockIdx.x * 128;
    const size_t base = (size_t)bh * 2048;
    const uint32_t smb = smem_u32(sw);

    attn_issue_tile(smb, 0, 0, tid, bh, base);
    CP_COMMIT();

    // stage Q into buffer-1 region; extract hi fragments only
    for (int i = tid; i < 2048; i += 256) {
        int r = i >> 4, ch = i & 15;
        *(uint4*)(sw + ABUF + r * RSA + ch * 4) =
            *(const uint4*)(QKiW + (base + n0 + r) * 64 + ch * 4);
    }
    __syncthreads();
    uint32_t qh[4][4];
    const int r0 = w * 16 + g;
    #pragma unroll
    for (int ks = 0; ks < 4; ks++) {
        uint4 a  = *(const uint4*)(sw + ABUF + r0 * RSA + 16 * ks + 4 * t);
        uint4 b2 = *(const uint4*)(sw + ABUF + (r0 + 8) * RSA + 16 * ks + 4 * t);
        qh[ks][0] = a.x;  qh[ks][1] = b2.x;  qh[ks][2] = a.y;  qh[ks][3] = b2.y;
    }
    const float tqa = Tqg[base + n0 + r0];
    const float tqb = Tqg[base + n0 + r0 + 8];

    float accO[9][4];
    #pragma unroll
    for (int nd = 0; nd < 9; nd++)
        #pragma unroll
        for (int c = 0; c < 4; c++) accO[nd][c] = 0.f;
    float lA = 0.f, lB = 0.f;

    for (int kt = 0; kt < 32; kt++) {
        const int cur = (kt & 1) * ABUF;
        CP_WAIT(0);
        __syncthreads();
        if (kt < 31) {
            attn_issue_tile(smb, ((kt + 1) & 1) * ABUF, kt + 1, tid, bh, base);
            CP_COMMIT();
        }

        const float* tks = (const float*)(sw + cur + TKOFF);

        float sacc[8][4];
        #pragma unroll
        for (int nt = 0; nt < 8; nt++)
            #pragma unroll
            for (int c = 0; c < 4; c++) sacc[nt][c] = 0.f;

        #pragma unroll
        for (int ks = 0; ks < 4; ks++) {
            #pragma unroll
            for (int nt = 0; nt < 8; nt++) {
                int n = nt * 8 + g;
                uint4 kv = *(const uint4*)(sw + cur + n * RSA + 16 * ks + 4 * t);
                uint32_t kb[2]  = { kv.x, kv.y };
                uint32_t klr[2] = { kv.z, kv.w };
                MMA16816(sacc[nt], qh[ks], kb);
                MMA16816(sacc[nt], qh[ks], klr);
            }
        }

        #pragma unroll
        for (int kb2 = 0; kb2 < 4; kb2++) {
            uint32_t Ahi[4];
            #pragma unroll
            for (int half = 0; half < 2; half++) {
                const int nt = 2 * kb2 + half;
                float2 tk = *(const float2*)(tks + nt * 8 + 2 * t);
                float e0 = exp2p((sacc[nt][0] - tqa * tk.x) * S2f);
                float e1 = exp2p((sacc[nt][1] - tqa * tk.y) * S2f);
                float e2 = exp2p((sacc[nt][2] - tqb * tk.x) * S2f);
                float e3 = exp2p((sacc[nt][3] - tqb * tk.y) * S2f);
                lA += e0 + e1;
                lB += e2 + e3;
                Ahi[half * 2 + 0] = cvtpk(e0, e1);
                Ahi[half * 2 + 1] = cvtpk(e2, e3);
            }
            #pragma unroll
            for (int nd = 0; nd < 9; nd++) {
                int n = nd * 8 + g;
                uint4 vv = *(const uint4*)(sw + cur + VOFF + n * RSA + 16 * kb2 + 4 * t);
                uint32_t vb[2] = { vv.x, vv.y };
                uint32_t vl[2] = { vv.z, vv.w };
                MMA16816(accO[nd], Ahi, vb);
                MMA16816(accO[nd], Ahi, vl);
            }
        }
    }

    lA += __shfl_xor_sync(0xffffffffu, lA, 1);
    lA += __shfl_xor_sync(0xffffffffu, lA, 2);
    lB += __shfl_xor_sync(0xffffffffu, lB, 1);
    lB += __shfl_xor_sync(0xffffffffu, lB, 2);

    const float linA = 1.f / lA, linB = 1.f / lB;
    float ssA = 0.f, ssB = 0.f;
    #pragma unroll
    for (int nd = 0; nd < 9; nd++) {
        accO[nd][0] *= linA;  accO[nd][1] *= linA;
        accO[nd][2] *= linB;  accO[nd][3] *= linB;
        ssA += accO[nd][0] * accO[nd][0] + accO[nd][1] * accO[nd][1];
        ssB += accO[nd][2] * accO[nd][2] + accO[nd][3] * accO[nd][3];
    }
    ssA += __shfl_xor_sync(0xffffffffu, ssA, 1);
    ssA += __shfl_xor_sync(0xffffffffu, ssA, 2);
    ssB += __shfl_xor_sync(0xffffffffu, ssB, 1);
    ssB += __shfl_xor_sync(0xffffffffu, ssB, 2);
    float tA = __shfl_sync(0xffffffffu, accO[0][0], lane & ~3);
    float tB = __shfl_sync(0xffffffffu, accO[0][2], lane & ~3);
    float spA = ssA - tA * tA;
    float spB = ssB - tB * tB;
    float idnA = rsqrtf(fmaxf(KCURV * (tA * tA - spA), EPSf));
    float idnB = rsqrtf(fmaxf(KCURV * (tB * tB - spB), EPSf));

    const int rowA = b * 2048 + n0 + w * 16 + g;
    const int rowB = rowA + 8;
    #pragma unroll
    for (int nd = 0; nd < 9; nd++) {
        #pragma unroll
        for (int c = 0; c < 2; c++) {
            int d = nd * 8 + 2 * t + c;
            if (d >= 1 && d < 65) {
                OutCat[(size_t)rowA * 512 + h * 64 + d - 1] = accO[nd][c] * idnA;
                OutCat[(size_t)rowB * 512 + h * 64 + d - 1] = accO[nd][c + 2] * idnB;
            }
        }
    }
    if (t == 0) {
        HSS[rowA * 8 + h] = spA * idnA * idnA;
        HSS[rowB * 8 + h] = spB * idnB * idnB;
    }
}

// =====================================================================
// K3: output projection (epilogue unchanged)
// =====================================================================
__global__ __launch_bounds__(256) void outproj_mma(
    const float* __restrict__ bo, float* __restrict__ out)
{
    extern __shared__ uint32_t smw[];
    const int tid = threadIdx.x;
    const int wid = tid >> 5, lane = tid & 31;
    const int wm = wid & 3, wn = wid >> 2;
    const int g = lane >> 2, t = lane & 3;
    const int m0 = blockIdx.x * 128;
    const int c0 = blockIdx.y * 64;

    if (tid < 64) ((float*)(smw + WBIAS))[tid] = bo[c0 + tid];

    float acc[2][4][4];
    #pragma unroll
    for (int mt = 0; mt < 2; mt++)
        #pragma unroll
        for (int nt = 0; nt < 4; nt++)
            #pragma unroll
            for (int i = 0; i < 4; i++) acc[mt][nt][i] = 0.f;

    gemm_mainloop(smw, tid,
                  Chi + (size_t)m0 * KPAD, Clo + (size_t)m0 * KPAD,
                  WoTHi + (size_t)c0 * KPAD, WoTLo + (size_t)c0 * KPAD,
                  acc);

    const float* biass = (const float*)(smw + WBIAS);
    float* ssP = (float*)(smw + WSSP);

    #pragma unroll
    for (int mt = 0; mt < 2; mt++) {
        #pragma unroll
        for (int half = 0; half < 2; half++) {
            int lrow = wm * 32 + mt * 16 + g + half * 8;
            int row = m0 + lrow;
            float ss = 0.f;
            #pragma unroll
            for (int nt = 0; nt < 4; nt++) {
                #pragma unroll
                for (int cc = 0; cc < 2; cc++) {
                    int col = wn * 32 + nt * 8 + 2 * t + cc;
                    float v = acc[mt][nt][half * 2 + cc] + biass[col];
                    out[(size_t)row * Dm + 1 + c0 + col] = v;
                    ss += v * v;
                }
            }
            ss += __shfl_xor_sync(0xffffffffu, ss, 1);
            ss += __shfl_xor_sync(0xffffffffu, ss, 2);
            if (t == 0) ssP[lrow * 2 + wn] = ss;
        }
    }
    __syncthreads();
    if (wn == 0 && t == 0) {
        #pragma unroll
        for (int mt = 0; mt < 2; mt++)
            #pragma unroll
            for (int half = 0; half < 2; half++) {
                int lrow = wm * 32 + mt * 16 + g + half * 8;
                int row = m0 + lrow;
                Part2[row * 8 + blockIdx.y] = ssP[lrow * 2] + ssP[lrow * 2 + 1];
            }
    }
}

__global__ void time_kernel(float* __restrict__ out)
{
    int row = blockIdx.x * 256 + threadIdx.x;
    if (row < Mrows) {
        float ss = 0.f;
        #pragma unroll
        for (int j = 0; j < 8; j++) ss += Part2[row * 8 + j];
        out[(size_t)row * Dm] = sqrtf(fmaxf(INVK + ss, EPSf));
    }
}

// =====================================================================
extern "C" void kernel_launch(void* const* d_in, const int* in_sizes, int n_in,
                              void* d_out, int out_size)
{
    const float* x  = (const float*)d_in[0];
    const float* Wq = (const float*)d_in[1];
    const float* bq = (const float*)d_in[2];
    const float* Wk = (const float*)d_in[3];
    const float* bk = (const float*)d_in[4];
    const float* Wv = (const float*)d_in[5];
    const float* bv = (const float*)d_in[6];
    const float* Wo = (const float*)d_in[7];
    const float* bo = (const float*)d_in[8];
    float* out = (float*)d_out;

    const int smem_gemm = WTOT * 4;
    const int smem_attn = 2 * ABUF * 4;
    cudaFuncSetAttribute(qkv_mma, cudaFuncAttributeMaxDynamicSharedMemorySize, smem_gemm);
    cudaFuncSetAttribute(outproj_mma, cudaFuncAttributeMaxDynamicSharedMemorySize, smem_gemm);
    cudaFuncSetAttribute(attn_mma, cudaFuncAttributeMaxDynamicSharedMemorySize, smem_attn);

    cvt_in_kernel<<<10240, 576>>>(Wq, Wk, Wv, Wo, x);
    qkv_mma<<<dim3(64, 24), 256, smem_gemm>>>(bq, bk, bv);
    vtrans<<<dim3(32, 32), 128>>>();
    attn_mma<<<dim3(16, 32), 256, smem_attn>>>();
    cvt_cat_kernel<<<8192, 576>>>();
    outproj_mma<<<dim3(64, 8), 256, smem_gemm>>>(bo, out);
    time_kernel<<<32, 256>>>(out);
}